// round 1
// baseline (speedup 1.0000x reference)
#include <cuda_runtime.h>
#include <math.h>

// Problem constants
#define BB 512
#define NN 64
#define MH 128   // MSG_HIDDEN == HIDDEN == 128

// Scratch (static __device__ arrays: allocation-free per harness rules)
__device__ float g_H[BB * NN * MH];        // 16 MB: sum_{j!=i} silu(pre_ij)
__device__ float g_Wfused[MH * MH];        // phi_w1 @ psi_w0[3:,:]
__device__ float g_c0[MH];                 // psi_b0 + 63 * phi_b1 @ psi_w0[3:,:]
__device__ float g_sp;                     // softplus(bf_scale_raw)

__device__ __forceinline__ float silu_f(float q) {
    // q * sigmoid(q) = q / (1 + exp(-q)); EX2 + RCP approx (~1e-7 rel)
    float e = __expf(-q);
    return __fdividef(q, 1.0f + e);
}

// ---------------------------------------------------------------------------
// Kernel 0: fold phi_w1 into psi_w0 rows 3.., fold biases, softplus scalar.
// grid = 129 blocks x 128 threads. ~2M FMA total, negligible.
// ---------------------------------------------------------------------------
__global__ void precompute_kernel(const float* __restrict__ phi_w1,
                                  const float* __restrict__ phi_b1,
                                  const float* __restrict__ psi_w0,
                                  const float* __restrict__ psi_b0,
                                  const float* __restrict__ bf_scale_raw)
{
    int o = threadIdx.x;
    int k = blockIdx.x;
    if (k < MH) {
        float acc = 0.0f;
        #pragma unroll 8
        for (int m = 0; m < MH; m++)
            acc = fmaf(phi_w1[k * MH + m], psi_w0[(3 + m) * MH + o], acc);
        g_Wfused[k * MH + o] = acc;
    } else {
        float acc = 0.0f;
        #pragma unroll 8
        for (int m = 0; m < MH; m++)
            acc = fmaf(phi_b1[m], psi_w0[(3 + m) * MH + o], acc);
        g_c0[o] = psi_b0[o] + 63.0f * acc;
        if (o == 0) {
            float v = bf_scale_raw[0];
            g_sp = (v > 20.0f) ? v : log1pf(__expf(v));
        }
    }
}

// ---------------------------------------------------------------------------
// Kernel 1: phi layer-1 + silu + sum over j (diagonal excluded).
// One block per batch b. 256 threads = 8 warps; warp w owns i = w*8..w*8+7,
// lane l owns channels k = 4l..4l+3.
// Shared: v_j[64][128] (32 KB) + r1[64][64] (16 KB) = 48 KB exactly.
// ---------------------------------------------------------------------------
__global__ __launch_bounds__(256) void phi_kernel(const float* __restrict__ x,
                                                  const float* __restrict__ W0,
                                                  const float* __restrict__ b0)
{
    __shared__ __align__(16) float vs[NN * MH];
    __shared__ __align__(16) float r1s[NN * NN];

    int b = blockIdx.x;
    int t = threadIdx.x;
    int w = t >> 5, l = t & 31;
    const float* xb = x + b * (NN * 3);

    // v_j[k] = sum_d xj_d * (W0[3+d,k] - W0[6+d,k])
    for (int idx = t; idx < NN * MH; idx += 256) {
        int j = idx >> 7, k = idx & 127;
        float xj0 = xb[j * 3 + 0], xj1 = xb[j * 3 + 1], xj2 = xb[j * 3 + 2];
        float vv = xj0 * (W0[3 * MH + k] - W0[6 * MH + k]);
        vv = fmaf(xj1, W0[4 * MH + k] - W0[7 * MH + k], vv);
        vv = fmaf(xj2, W0[5 * MH + k] - W0[8 * MH + k], vv);
        vs[idx] = vv;
    }
    // r1[i][j] = sqrt(|xi-xj|^2 + 1e-12)
    for (int idx = t; idx < NN * NN; idx += 256) {
        int i = idx >> 6, j = idx & 63;
        float d0 = xb[i * 3 + 0] - xb[j * 3 + 0];
        float d1 = xb[i * 3 + 1] - xb[j * 3 + 1];
        float d2 = xb[i * 3 + 2] - xb[j * 3 + 2];
        r1s[idx] = sqrtf(fmaf(d0, d0, fmaf(d1, d1, fmaf(d2, d2, 1e-12f))));
    }

    // Per-lane weight slices (channels 4l..4l+3), kept in registers
    int kc = l * 4;
    float ws0[4], ws1[4], ws2[4], w9[4], w10[4], bbv[4];
    #pragma unroll
    for (int c = 0; c < 4; c++) {
        int k = kc + c;
        ws0[c] = W0[0 * MH + k] + W0[6 * MH + k];
        ws1[c] = W0[1 * MH + k] + W0[7 * MH + k];
        ws2[c] = W0[2 * MH + k] + W0[8 * MH + k];
        w9[c]  = W0[9 * MH + k];
        w10[c] = W0[10 * MH + k];
        bbv[c] = b0[k];
    }
    __syncthreads();

    const float4* vs4 = (const float4*)vs;
    for (int ii = 0; ii < 8; ii++) {
        int i = w * 8 + ii;
        float xi0 = xb[i * 3 + 0], xi1 = xb[i * 3 + 1], xi2 = xb[i * 3 + 2];
        float u[4], acc[4];
        #pragma unroll
        for (int c = 0; c < 4; c++) {
            u[c] = fmaf(xi2, ws2[c], fmaf(xi1, ws1[c], fmaf(xi0, ws0[c], bbv[c])));
            acc[c] = 0.0f;
        }
        // branch-free full sum over all j (diagonal subtracted below)
        #pragma unroll 4
        for (int j = 0; j < NN; j++) {
            float r1 = r1s[i * NN + j];
            float r2 = fmaf(r1, r1, -1e-12f);
            float4 v4 = vs4[j * 32 + l];
            float vv[4] = {v4.x, v4.y, v4.z, v4.w};
            #pragma unroll
            for (int c = 0; c < 4; c++) {
                float q = fmaf(r1, w9[c], fmaf(r2, w10[c], u[c] + vv[c]));
                acc[c] += silu_f(q);
            }
        }
        // subtract the i==i term (same shared r1 value -> same q bitwise)
        {
            float r1 = r1s[i * NN + i];
            float r2 = fmaf(r1, r1, -1e-12f);
            float4 v4 = vs4[i * 32 + l];
            float vv[4] = {v4.x, v4.y, v4.z, v4.w};
            #pragma unroll
            for (int c = 0; c < 4; c++) {
                float q = fmaf(r1, w9[c], fmaf(r2, w10[c], u[c] + vv[c]));
                acc[c] -= silu_f(q);
            }
        }
        float4 o4 = make_float4(acc[0], acc[1], acc[2], acc[3]);
        *(float4*)(g_H + ((size_t)(b * NN + i)) * MH + kc) = o4;
    }
}

// ---------------------------------------------------------------------------
// Kernel 2: psi MLP (with fused W1): one block per batch b, 256 threads.
// Warp w owns rows r = w*8..w*8+7; lane l owns cols 4l..4l+3.
// h1 = silu(x @ psi_w0[0:3] + H @ Wfused + c0)
// h2 = silu(h1 @ psi_w1 + psi_b1)
// out = tanh(h2 @ psi_w2 + psi_b2) * softplus(bf_scale_raw)
// ---------------------------------------------------------------------------
__global__ __launch_bounds__(256) void psi_kernel(const float* __restrict__ x,
                                                  const float* __restrict__ psi_w0,
                                                  const float* __restrict__ psi_w1,
                                                  const float* __restrict__ psi_b1,
                                                  const float* __restrict__ psi_w2,
                                                  const float* __restrict__ psi_b2,
                                                  float* __restrict__ out)
{
    __shared__ __align__(16) float sb[NN * MH];
    int b = blockIdx.x;
    int t = threadIdx.x;
    int w = t >> 5, l = t & 31;
    int r0 = w * 8;
    int c0i = l * 4;

    // Load H tile to shared (coalesced float4)
    {
        const float4* Hg = (const float4*)(g_H + (size_t)b * NN * MH);
        float4* sb4 = (float4*)sb;
        for (int idx = t; idx < NN * MH / 4; idx += 256) sb4[idx] = Hg[idx];
    }
    __syncthreads();

    float acc[8][4];
    // init: c0 + x @ psi_w0[0:3]
    {
        float4 wc  = *(const float4*)(g_c0 + c0i);
        float4 px0 = *(const float4*)(psi_w0 + 0 * MH + c0i);
        float4 px1 = *(const float4*)(psi_w0 + 1 * MH + c0i);
        float4 px2 = *(const float4*)(psi_w0 + 2 * MH + c0i);
        #pragma unroll
        for (int rr = 0; rr < 8; rr++) {
            int r = r0 + rr;
            float x0 = x[(b * NN + r) * 3 + 0];
            float x1 = x[(b * NN + r) * 3 + 1];
            float x2 = x[(b * NN + r) * 3 + 2];
            acc[rr][0] = fmaf(x2, px2.x, fmaf(x1, px1.x, fmaf(x0, px0.x, wc.x)));
            acc[rr][1] = fmaf(x2, px2.y, fmaf(x1, px1.y, fmaf(x0, px0.y, wc.y)));
            acc[rr][2] = fmaf(x2, px2.z, fmaf(x1, px1.z, fmaf(x0, px0.z, wc.z)));
            acc[rr][3] = fmaf(x2, px2.w, fmaf(x1, px1.w, fmaf(x0, px0.w, wc.w)));
        }
    }
    // layer A: += H @ Wfused
    #pragma unroll 2
    for (int k = 0; k < MH; k++) {
        float4 wv = *(const float4*)(g_Wfused + k * MH + c0i);
        #pragma unroll
        for (int rr = 0; rr < 8; rr++) {
            float a = sb[(r0 + rr) * MH + k];   // warp-broadcast LDS
            acc[rr][0] = fmaf(a, wv.x, acc[rr][0]);
            acc[rr][1] = fmaf(a, wv.y, acc[rr][1]);
            acc[rr][2] = fmaf(a, wv.z, acc[rr][2]);
            acc[rr][3] = fmaf(a, wv.w, acc[rr][3]);
        }
    }
    #pragma unroll
    for (int rr = 0; rr < 8; rr++)
        #pragma unroll
        for (int c = 0; c < 4; c++)
            acc[rr][c] = silu_f(acc[rr][c]);

    __syncthreads();
    #pragma unroll
    for (int rr = 0; rr < 8; rr++)
        *(float4*)&sb[(r0 + rr) * MH + c0i] =
            make_float4(acc[rr][0], acc[rr][1], acc[rr][2], acc[rr][3]);
    __syncthreads();

    // layer B: h2 = silu(h1 @ psi_w1 + psi_b1)
    {
        float4 bv = *(const float4*)(psi_b1 + c0i);
        #pragma unroll
        for (int rr = 0; rr < 8; rr++) {
            acc[rr][0] = bv.x; acc[rr][1] = bv.y;
            acc[rr][2] = bv.z; acc[rr][3] = bv.w;
        }
    }
    #pragma unroll 2
    for (int k = 0; k < MH; k++) {
        float4 wv = *(const float4*)(psi_w1 + k * MH + c0i);
        #pragma unroll
        for (int rr = 0; rr < 8; rr++) {
            float a = sb[(r0 + rr) * MH + k];
            acc[rr][0] = fmaf(a, wv.x, acc[rr][0]);
            acc[rr][1] = fmaf(a, wv.y, acc[rr][1]);
            acc[rr][2] = fmaf(a, wv.z, acc[rr][2]);
            acc[rr][3] = fmaf(a, wv.w, acc[rr][3]);
        }
    }
    #pragma unroll
    for (int rr = 0; rr < 8; rr++)
        #pragma unroll
        for (int c = 0; c < 4; c++)
            acc[rr][c] = silu_f(acc[rr][c]);

    // layer C: tanh(h2 @ psi_w2 + b2) * sp, warp-shuffle reduction (rows are
    // entirely warp-local: lane l holds cols 4l..4l+3 of each of its 8 rows)
    float w2v[4][3];
    #pragma unroll
    for (int cc = 0; cc < 4; cc++)
        #pragma unroll
        for (int oc = 0; oc < 3; oc++)
            w2v[cc][oc] = psi_w2[(c0i + cc) * 3 + oc];

    float sp = g_sp;
    #pragma unroll
    for (int rr = 0; rr < 8; rr++) {
        #pragma unroll
        for (int oc = 0; oc < 3; oc++) {
            float p = acc[rr][0] * w2v[0][oc];
            p = fmaf(acc[rr][1], w2v[1][oc], p);
            p = fmaf(acc[rr][2], w2v[2][oc], p);
            p = fmaf(acc[rr][3], w2v[3][oc], p);
            #pragma unroll
            for (int off = 16; off; off >>= 1)
                p += __shfl_xor_sync(0xffffffffu, p, off);
            if (l == 0) {
                float y = tanhf(p + psi_b2[oc]);
                out[((b * NN) + (r0 + rr)) * 3 + oc] = y * sp;
            }
        }
    }
}

// ---------------------------------------------------------------------------
// Launch. Inputs (metadata order): 0 x, 1 spin(unused), 2 phi_w0, 3 phi_b0,
// 4 phi_w1, 5 phi_b1, 6 psi_w0, 7 psi_b0, 8 psi_w1, 9 psi_b1, 10 psi_w2,
// 11 psi_b2, 12 bf_scale_raw. Output: float32 (512,64,3).
// ---------------------------------------------------------------------------
extern "C" void kernel_launch(void* const* d_in, const int* in_sizes, int n_in,
                              void* d_out, int out_size)
{
    const float* x      = (const float*)d_in[0];
    const float* phi_w0 = (const float*)d_in[2];
    const float* phi_b0 = (const float*)d_in[3];
    const float* phi_w1 = (const float*)d_in[4];
    const float* phi_b1 = (const float*)d_in[5];
    const float* psi_w0 = (const float*)d_in[6];
    const float* psi_b0 = (const float*)d_in[7];
    const float* psi_w1 = (const float*)d_in[8];
    const float* psi_b1 = (const float*)d_in[9];
    const float* psi_w2 = (const float*)d_in[10];
    const float* psi_b2 = (const float*)d_in[11];
    const float* bf     = (const float*)d_in[12];
    float* out = (float*)d_out;

    precompute_kernel<<<129, 128>>>(phi_w1, phi_b1, psi_w0, psi_b0, bf);
    phi_kernel<<<BB, 256>>>(x, phi_w0, phi_b0);
    psi_kernel<<<BB, 256>>>(x, psi_w0, psi_w1, psi_b1, psi_w2, psi_b2, out);
}

// round 2
// speedup vs baseline: 1.6405x; 1.6405x over previous
#include <cuda_runtime.h>
#include <math.h>

#define BB 512
#define NN 64
#define MH 128

// Scratch (allocation-free per harness rules)
__device__ float g_Wfused[MH * MH];        // phi_w1 @ psi_w0[3:,:]
__device__ float g_c0[MH];                 // psi_b0 + 63 * phi_b1 @ psi_w0[3:,:]
__device__ float g_sp;                     // softplus(bf_scale_raw)

__device__ __forceinline__ float tanh_apx(float v) {
    float y;
    asm("tanh.approx.f32 %0, %1;" : "=f"(y) : "f"(v));
    return y;
}
// silu(q) = 0.5q(1+tanh(0.5q)); used only in psi (phi inlines the halved form)
__device__ __forceinline__ float silu_f(float q) {
    float qh = 0.5f * q;
    float th = tanh_apx(qh);
    return fmaf(qh, th, qh);
}

// ---------------------------------------------------------------------------
// Kernel 0: Wfused = phi_w1 @ psi_w0[3:], c0 = psi_b0 + 63*phi_b1@psi_w0[3:],
// sp = softplus(bf_scale_raw). Shared-staged, coalesced.
// ---------------------------------------------------------------------------
__global__ __launch_bounds__(128) void precompute_kernel(
    const float* __restrict__ phi_w1, const float* __restrict__ phi_b1,
    const float* __restrict__ psi_w0, const float* __restrict__ psi_b0,
    const float* __restrict__ bf_scale_raw)
{
    __shared__ float row[MH];
    int t = threadIdx.x;
    int k = blockIdx.x;
    const float* src = (k < MH) ? (phi_w1 + k * MH) : phi_b1;
    row[t] = src[t];
    __syncthreads();

    float a0 = 0.f, a1 = 0.f, a2 = 0.f, a3 = 0.f;
    #pragma unroll 8
    for (int m = 0; m < MH; m += 4) {
        a0 = fmaf(row[m + 0], psi_w0[(3 + m + 0) * MH + t], a0);
        a1 = fmaf(row[m + 1], psi_w0[(3 + m + 1) * MH + t], a1);
        a2 = fmaf(row[m + 2], psi_w0[(3 + m + 2) * MH + t], a2);
        a3 = fmaf(row[m + 3], psi_w0[(3 + m + 3) * MH + t], a3);
    }
    float acc = (a0 + a1) + (a2 + a3);
    if (k < MH) {
        g_Wfused[k * MH + t] = acc;
    } else {
        g_c0[t] = psi_b0[t] + 63.0f * acc;
        if (t == 0) {
            float v = bf_scale_raw[0];
            g_sp = (v > 20.0f) ? v : log1pf(__expf(v));
        }
    }
}

// ---------------------------------------------------------------------------
// Fused kernel: one block per batch b (512 blocks x 256 threads).
// Phase 1 (phi): warp w owns rows i = w*8..w*8+7, lane l owns channels 4l..4l+3.
//   All weights pre-halved so q' = q/2; silu(q) = q' + q'*tanh(q').
//   H = sum_{j != i} silu(pre_ij), accumulated branch-free, diagonal subtracted.
// Phase 2 (psi): H staged in shared (overlaid on vs), 3-layer MLP.
// Shared: vs[64][128] (32KB, reused as sb) + r1s[64][64] (16KB) = 48KB.
// ---------------------------------------------------------------------------
__global__ __launch_bounds__(256, 2) void fused_kernel(
    const float* __restrict__ x,
    const float* __restrict__ W0, const float* __restrict__ b0,
    const float* __restrict__ psi_w0,
    const float* __restrict__ psi_w1, const float* __restrict__ psi_b1,
    const float* __restrict__ psi_w2, const float* __restrict__ psi_b2,
    float* __restrict__ out)
{
    __shared__ __align__(16) float vs[NN * MH];    // phase1: v'_j ; phase2: h
    __shared__ __align__(16) float r1s[NN * NN];   // [j][i] (symmetric)

    int b = blockIdx.x;
    int t = threadIdx.x;
    int w = t >> 5, l = t & 31;
    int r0 = w * 8;
    int kc = l * 4;
    const float* xb = x + b * (NN * 3);

    // ---------------- Phase 1 setup ----------------
    // vs[j][k] = 0.5 * sum_d xj_d * (W0[3+d,k] - W0[6+d,k])
    for (int idx = t; idx < NN * MH; idx += 256) {
        int j = idx >> 7, k = idx & 127;
        float xj0 = xb[j * 3 + 0], xj1 = xb[j * 3 + 1], xj2 = xb[j * 3 + 2];
        float vv = xj0 * (W0[3 * MH + k] - W0[6 * MH + k]);
        vv = fmaf(xj1, W0[4 * MH + k] - W0[7 * MH + k], vv);
        vv = fmaf(xj2, W0[5 * MH + k] - W0[8 * MH + k], vv);
        vs[idx] = 0.5f * vv;
    }
    // r1s[j][i] = sqrt(|xi-xj|^2 + 1e-12)  (symmetric, bitwise both ways)
    for (int idx = t; idx < NN * NN; idx += 256) {
        int j = idx >> 6, i = idx & 63;
        float d0 = xb[i * 3 + 0] - xb[j * 3 + 0];
        float d1 = xb[i * 3 + 1] - xb[j * 3 + 1];
        float d2 = xb[i * 3 + 2] - xb[j * 3 + 2];
        r1s[idx] = sqrtf(fmaf(d0, d0, fmaf(d1, d1, fmaf(d2, d2, 1e-12f))));
    }

    // per-lane halved channel weights
    float w9h[4], w10h[4];
    float u[8][4];   // u'[row][c] = 0.5*(b0 + xi . (W0[0:3]+W0[6:9]))
    {
        float ws0[4], ws1[4], ws2[4], bh[4];
        #pragma unroll
        for (int c = 0; c < 4; c++) {
            int k = kc + c;
            ws0[c] = 0.5f * (W0[0 * MH + k] + W0[6 * MH + k]);
            ws1[c] = 0.5f * (W0[1 * MH + k] + W0[7 * MH + k]);
            ws2[c] = 0.5f * (W0[2 * MH + k] + W0[8 * MH + k]);
            w9h[c]  = 0.5f * W0[9 * MH + k];
            w10h[c] = 0.5f * W0[10 * MH + k];
            bh[c]  = 0.5f * b0[k];
        }
        #pragma unroll
        for (int ii = 0; ii < 8; ii++) {
            int i = r0 + ii;
            float xi0 = xb[i * 3 + 0], xi1 = xb[i * 3 + 1], xi2 = xb[i * 3 + 2];
            #pragma unroll
            for (int c = 0; c < 4; c++)
                u[ii][c] = fmaf(xi2, ws2[c],
                           fmaf(xi1, ws1[c], fmaf(xi0, ws0[c], bh[c])));
        }
    }
    __syncthreads();

    // ---------------- Phase 1 main loop (j outer) ----------------
    float acc[8][4];
    #pragma unroll
    for (int ii = 0; ii < 8; ii++)
        #pragma unroll
        for (int c = 0; c < 4; c++) acc[ii][c] = 0.0f;

    const float4* vs4 = (const float4*)vs;
    #pragma unroll 2
    for (int j = 0; j < NN; j++) {
        float4 v4 = vs4[j * 32 + l];
        float vc[4] = {v4.x, v4.y, v4.z, v4.w};
        float4 ra = *(const float4*)&r1s[j * NN + r0];      // broadcast
        float4 rb = *(const float4*)&r1s[j * NN + r0 + 4];
        float r1v[8] = {ra.x, ra.y, ra.z, ra.w, rb.x, rb.y, rb.z, rb.w};
        #pragma unroll
        for (int ii = 0; ii < 8; ii++) {
            float r1 = r1v[ii];
            float r2 = fmaf(r1, r1, -1e-12f);
            #pragma unroll
            for (int c = 0; c < 4; c++) {
                float qh = fmaf(r1, w9h[c], fmaf(r2, w10h[c], u[ii][c] + vc[c]));
                float th = tanh_apx(qh);
                acc[ii][c] = fmaf(qh, th, acc[ii][c] + qh);
            }
        }
    }
    // subtract diagonal term (same inputs -> same qh up to rounding)
    #pragma unroll
    for (int ii = 0; ii < 8; ii++) {
        int i = r0 + ii;
        float4 v4 = vs4[i * 32 + l];
        float vc[4] = {v4.x, v4.y, v4.z, v4.w};
        float r1 = r1s[i * NN + i];
        float r2 = fmaf(r1, r1, -1e-12f);
        #pragma unroll
        for (int c = 0; c < 4; c++) {
            float qh = fmaf(r1, w9h[c], fmaf(r2, w10h[c], u[ii][c] + vc[c]));
            float th = tanh_apx(qh);
            acc[ii][c] -= fmaf(qh, th, qh);
        }
    }

    // ---------------- stage H into shared (overlay vs) ----------------
    __syncthreads();   // all vs reads done
    float* sb = vs;
    #pragma unroll
    for (int ii = 0; ii < 8; ii++)
        *(float4*)&sb[(r0 + ii) * MH + kc] =
            make_float4(acc[ii][0], acc[ii][1], acc[ii][2], acc[ii][3]);
    __syncthreads();

    // ---------------- Phase 2: psi ----------------
    const float4* sb4 = (const float4*)sb;

    // init: c0 + x @ psi_w0[0:3]
    {
        float4 wc  = *(const float4*)(g_c0 + kc);
        float4 px0 = *(const float4*)(psi_w0 + 0 * MH + kc);
        float4 px1 = *(const float4*)(psi_w0 + 1 * MH + kc);
        float4 px2 = *(const float4*)(psi_w0 + 2 * MH + kc);
        #pragma unroll
        for (int rr = 0; rr < 8; rr++) {
            int r = r0 + rr;
            float x0 = xb[r * 3 + 0], x1 = xb[r * 3 + 1], x2 = xb[r * 3 + 2];
            acc[rr][0] = fmaf(x2, px2.x, fmaf(x1, px1.x, fmaf(x0, px0.x, wc.x)));
            acc[rr][1] = fmaf(x2, px2.y, fmaf(x1, px1.y, fmaf(x0, px0.y, wc.y)));
            acc[rr][2] = fmaf(x2, px2.z, fmaf(x1, px1.z, fmaf(x0, px0.z, wc.z)));
            acc[rr][3] = fmaf(x2, px2.w, fmaf(x1, px1.w, fmaf(x0, px0.w, wc.w)));
        }
    }
    // layer A: += H @ Wfused   (k in groups of 4, float4 LDS of activations)
    #pragma unroll 1
    for (int k4 = 0; k4 < MH / 4; k4++) {
        float4 a[8];
        #pragma unroll
        for (int rr = 0; rr < 8; rr++) a[rr] = sb4[(r0 + rr) * 32 + k4];
        #pragma unroll
        for (int kk = 0; kk < 4; kk++) {
            float4 wv = *(const float4*)(g_Wfused + (k4 * 4 + kk) * MH + kc);
            #pragma unroll
            for (int rr = 0; rr < 8; rr++) {
                float av = (kk == 0) ? a[rr].x : (kk == 1) ? a[rr].y
                         : (kk == 2) ? a[rr].z : a[rr].w;
                acc[rr][0] = fmaf(av, wv.x, acc[rr][0]);
                acc[rr][1] = fmaf(av, wv.y, acc[rr][1]);
                acc[rr][2] = fmaf(av, wv.z, acc[rr][2]);
                acc[rr][3] = fmaf(av, wv.w, acc[rr][3]);
            }
        }
    }
    #pragma unroll
    for (int rr = 0; rr < 8; rr++)
        #pragma unroll
        for (int c = 0; c < 4; c++) acc[rr][c] = silu_f(acc[rr][c]);

    __syncthreads();
    #pragma unroll
    for (int rr = 0; rr < 8; rr++)
        *(float4*)&sb[(r0 + rr) * MH + kc] =
            make_float4(acc[rr][0], acc[rr][1], acc[rr][2], acc[rr][3]);
    __syncthreads();

    // layer B: h2 = silu(h1 @ psi_w1 + psi_b1)
    {
        float4 bv = *(const float4*)(psi_b1 + kc);
        #pragma unroll
        for (int rr = 0; rr < 8; rr++) {
            acc[rr][0] = bv.x; acc[rr][1] = bv.y;
            acc[rr][2] = bv.z; acc[rr][3] = bv.w;
        }
    }
    #pragma unroll 1
    for (int k4 = 0; k4 < MH / 4; k4++) {
        float4 a[8];
        #pragma unroll
        for (int rr = 0; rr < 8; rr++) a[rr] = sb4[(r0 + rr) * 32 + k4];
        #pragma unroll
        for (int kk = 0; kk < 4; kk++) {
            float4 wv = *(const float4*)(psi_w1 + (k4 * 4 + kk) * MH + kc);
            #pragma unroll
            for (int rr = 0; rr < 8; rr++) {
                float av = (kk == 0) ? a[rr].x : (kk == 1) ? a[rr].y
                         : (kk == 2) ? a[rr].z : a[rr].w;
                acc[rr][0] = fmaf(av, wv.x, acc[rr][0]);
                acc[rr][1] = fmaf(av, wv.y, acc[rr][1]);
                acc[rr][2] = fmaf(av, wv.z, acc[rr][2]);
                acc[rr][3] = fmaf(av, wv.w, acc[rr][3]);
            }
        }
    }
    #pragma unroll
    for (int rr = 0; rr < 8; rr++)
        #pragma unroll
        for (int c = 0; c < 4; c++) acc[rr][c] = silu_f(acc[rr][c]);

    // layer C: tanh(h2 @ psi_w2 + b2) * sp; warp-shuffle reduce (row warp-local)
    float w2v[4][3];
    #pragma unroll
    for (int cc = 0; cc < 4; cc++)
        #pragma unroll
        for (int oc = 0; oc < 3; oc++)
            w2v[cc][oc] = psi_w2[(kc + cc) * 3 + oc];

    float sp = g_sp;
    #pragma unroll
    for (int rr = 0; rr < 8; rr++) {
        #pragma unroll
        for (int oc = 0; oc < 3; oc++) {
            float p = acc[rr][0] * w2v[0][oc];
            p = fmaf(acc[rr][1], w2v[1][oc], p);
            p = fmaf(acc[rr][2], w2v[2][oc], p);
            p = fmaf(acc[rr][3], w2v[3][oc], p);
            #pragma unroll
            for (int off = 16; off; off >>= 1)
                p += __shfl_xor_sync(0xffffffffu, p, off);
            if (l == 0) {
                float y = tanhf(p + psi_b2[oc]);
                out[((b * NN) + (r0 + rr)) * 3 + oc] = y * sp;
            }
        }
    }
}

// ---------------------------------------------------------------------------
// Inputs (metadata order): 0 x, 1 spin(unused), 2 phi_w0, 3 phi_b0, 4 phi_w1,
// 5 phi_b1, 6 psi_w0, 7 psi_b0, 8 psi_w1, 9 psi_b1, 10 psi_w2, 11 psi_b2,
// 12 bf_scale_raw. Output: float32 (512,64,3).
// ---------------------------------------------------------------------------
extern "C" void kernel_launch(void* const* d_in, const int* in_sizes, int n_in,
                              void* d_out, int out_size)
{
    const float* x      = (const float*)d_in[0];
    const float* phi_w0 = (const float*)d_in[2];
    const float* phi_b0 = (const float*)d_in[3];
    const float* phi_w1 = (const float*)d_in[4];
    const float* phi_b1 = (const float*)d_in[5];
    const float* psi_w0 = (const float*)d_in[6];
    const float* psi_b0 = (const float*)d_in[7];
    const float* psi_w1 = (const float*)d_in[8];
    const float* psi_b1 = (const float*)d_in[9];
    const float* psi_w2 = (const float*)d_in[10];
    const float* psi_b2 = (const float*)d_in[11];
    const float* bf     = (const float*)d_in[12];
    float* out = (float*)d_out;

    precompute_kernel<<<MH + 1, MH>>>(phi_w1, phi_b1, psi_w0, psi_b0, bf);
    fused_kernel<<<BB, 256>>>(x, phi_w0, phi_b0, psi_w0,
                              psi_w1, psi_b1, psi_w2, psi_b2, out);
}